// round 11
// baseline (speedup 1.0000x reference)
#include <cuda_runtime.h>
#include <math_constants.h>

// Heatmaps_57363583205469: 3x3 max-pool peak mask + sigmoid gating.
//   keep = (maxpool3x3(h) == h) && (sigmoid(h) > 0.05)
//   out  = keep ? sigmoid(h) : 0
// Shapes: [16, 17, 512, 512] fp32 -> 272 planes of 512x512.
//
// R10: R4 operating point (128 thr x 4 cols float4, 64-row strips,
// unroll 4, default cache ops — the proven best schedule), with the warp
// shuffles replaced by two scalar neighbor LDGs. The scalars hit lines the
// same warp's LDG.128s are already fetching (miss-merge, zero extra DRAM
// traffic), removing the shfl convergence/serialization and all lane-0/31
// predication from the hot loop. Rolling 3-row register window; no smem,
// no barriers.

#define W 512
#define H 512
#define ROWS_PER_BLOCK 64
// logit(0.05f) computed in double precision: -ln(1/0.05000000074505806 - 1)
#define XTHRESH (-2.9444389643f)

__device__ __forceinline__ float4 row_hmax(const float* __restrict__ row,
                                           int c0, float4& v)
{
    v = __ldg(reinterpret_cast<const float4*>(row + c0));
    // Neighbor elements via scalar loads: same 128B lines as the warp's
    // vector loads -> L1 hit / miss-merge. No shuffles, no convergence.
    float l = (c0 == 0)     ? -CUDART_INF_F : __ldg(row + c0 - 1);
    float r = (c0 + 4 >= W) ? -CUDART_INF_F : __ldg(row + c0 + 4);
    float4 h;
    h.x = fmaxf(fmaxf(l,   v.x), v.y);
    h.y = fmaxf(fmaxf(v.x, v.y), v.z);
    h.z = fmaxf(fmaxf(v.y, v.z), v.w);
    h.w = fmaxf(fmaxf(v.z, v.w), r);
    return h;
}

__device__ __forceinline__ float peak_val(float m, float v)
{
    // sigmoid via fast EX2 + RCP (2 MUFU) — rel err ~1e-6, hides under DRAM.
    float s = __fdividef(1.0f, 1.0f + __expf(-v));
    return (m == v && v > XTHRESH) ? s : 0.0f;
}

__global__ void __launch_bounds__(128)
Heatmaps_57363583205469_kernel(const float* __restrict__ in,
                               float* __restrict__ out)
{
    const int plane = blockIdx.y;                 // 0..271  (B*K planes)
    const int strip = blockIdx.x;                 // 0..7    (64-row strips)
    const int c0    = threadIdx.x << 2;           // 4 cols per thread

    const float* __restrict__ base  = in  + (size_t)plane * (W * H);
    float*       __restrict__ obase = out + (size_t)plane * (W * H);
    const int r0 = strip * ROWS_PER_BLOCK;

    const float4 ninf = make_float4(-CUDART_INF_F, -CUDART_INF_F,
                                    -CUDART_INF_F, -CUDART_INF_F);

    float4 v_curr, v_next, v_scratch;
    float4 h_prev, h_curr, h_next;

    h_prev = (r0 == 0) ? ninf
                       : row_hmax(base + (size_t)(r0 - 1) * W, c0, v_scratch);
    h_curr = row_hmax(base + (size_t)r0 * W, c0, v_curr);

    #pragma unroll 4
    for (int r = r0; r < r0 + ROWS_PER_BLOCK; ++r) {
        if (r + 1 < H) {
            h_next = row_hmax(base + (size_t)(r + 1) * W, c0, v_next);
        } else {
            h_next = ninf;
            v_next = ninf;
        }

        float4 o;
        o.x = peak_val(fmaxf(fmaxf(h_prev.x, h_curr.x), h_next.x), v_curr.x);
        o.y = peak_val(fmaxf(fmaxf(h_prev.y, h_curr.y), h_next.y), v_curr.y);
        o.z = peak_val(fmaxf(fmaxf(h_prev.z, h_curr.z), h_next.z), v_curr.z);
        o.w = peak_val(fmaxf(fmaxf(h_prev.w, h_curr.w), h_next.w), v_curr.w);

        *reinterpret_cast<float4*>(obase + (size_t)r * W + c0) = o;

        h_prev = h_curr;
        h_curr = h_next;
        v_curr = v_next;
    }
}

extern "C" void kernel_launch(void* const* d_in, const int* in_sizes, int n_in,
                              void* d_out, int out_size)
{
    const float* in  = (const float*)d_in[0];
    float*       out = (float*)d_out;
    const int planes = in_sizes[0] / (W * H);     // 16 * 17 = 272

    dim3 grid(H / ROWS_PER_BLOCK, planes);
    Heatmaps_57363583205469_kernel<<<grid, 128>>>(in, out);
}

// round 13
// speedup vs baseline: 1.2585x; 1.2585x over previous
#include <cuda_runtime.h>
#include <math_constants.h>

// Heatmaps_57363583205469: 3x3 max-pool peak mask + sigmoid gating.
//   keep = (maxpool3x3(h) == h) && (sigmoid(h) > 0.05)
//   out  = keep ? sigmoid(h) : 0
// Shapes: [16, 17, 512, 512] fp32 -> 272 planes of 512x512.
//
// FINAL (R8 schedule, best measured: ncu 94.4us, bench 98.8us, DRAM 70.7%):
//  - 128 thr x 4 cols (float4), 64-row strips, unroll 4: regs=32 ->
//    16 CTAs/SM possible, whole 2176-CTA grid resident in ONE wave.
//  - Horizontal 3-max via 2 warp shuffles (cheapest neighbor path: scalar
//    LDG alternatives triple the L1tex queue depth and tail the wave).
//  - Vertical 3-max via rolling 3-row register window; each input element
//    read once from DRAM (+3% strip halo, L2-served).
//  - __stcs on the zero-reuse write stream (evict-first).
//  - MLP_p1=4: below the cross-CTA L1tex queue-contention knee (unroll 8
//    regressed 20%). No smem, no barriers.
// Measured ceiling: ~5.6 TB/s = HBM r/w-turnaround limit for 1:1 mix;
// all compute pipes <36% (overlapped, non-binding).

#define W 512
#define H 512
#define ROWS_PER_BLOCK 64
// logit(0.05f) computed in double precision: -ln(1/0.05000000074505806 - 1)
#define XTHRESH (-2.9444389643f)

__device__ __forceinline__ float4 row_hmax(const float* __restrict__ row,
                                           int c0, int lane, float4& v)
{
    v = __ldg(reinterpret_cast<const float4*>(row + c0));
    float l = __shfl_up_sync(0xffffffffu, v.w, 1);
    float r = __shfl_down_sync(0xffffffffu, v.x, 1);
    if (lane == 0)  l = (c0 == 0)       ? -CUDART_INF_F : __ldg(row + c0 - 1);
    if (lane == 31) r = (c0 + 4 >= W)   ? -CUDART_INF_F : __ldg(row + c0 + 4);
    float4 h;
    h.x = fmaxf(fmaxf(l,   v.x), v.y);
    h.y = fmaxf(fmaxf(v.x, v.y), v.z);
    h.z = fmaxf(fmaxf(v.y, v.z), v.w);
    h.w = fmaxf(fmaxf(v.z, v.w), r);
    return h;
}

__device__ __forceinline__ float peak_val(float m, float v)
{
    // sigmoid via fast EX2 + RCP (2 MUFU) — rel err ~1e-6, hides under DRAM.
    float s = __fdividef(1.0f, 1.0f + __expf(-v));
    return (m == v && v > XTHRESH) ? s : 0.0f;
}

__global__ void __launch_bounds__(128)
Heatmaps_57363583205469_kernel(const float* __restrict__ in,
                               float* __restrict__ out)
{
    const int plane = blockIdx.y;                 // 0..271  (B*K planes)
    const int strip = blockIdx.x;                 // 0..7    (64-row strips)
    const int lane  = threadIdx.x & 31;
    const int c0    = threadIdx.x << 2;           // 4 cols per thread

    const float* __restrict__ base  = in  + (size_t)plane * (W * H);
    float*       __restrict__ obase = out + (size_t)plane * (W * H);
    const int r0 = strip * ROWS_PER_BLOCK;

    const float4 ninf = make_float4(-CUDART_INF_F, -CUDART_INF_F,
                                    -CUDART_INF_F, -CUDART_INF_F);

    float4 v_curr, v_next, v_scratch;
    float4 h_prev, h_curr, h_next;

    h_prev = (r0 == 0) ? ninf
                       : row_hmax(base + (size_t)(r0 - 1) * W, c0, lane, v_scratch);
    h_curr = row_hmax(base + (size_t)r0 * W, c0, lane, v_curr);

    #pragma unroll 4
    for (int r = r0; r < r0 + ROWS_PER_BLOCK; ++r) {
        if (r + 1 < H) {
            h_next = row_hmax(base + (size_t)(r + 1) * W, c0, lane, v_next);
        } else {
            h_next = ninf;
            v_next = ninf;
        }

        float4 o;
        o.x = peak_val(fmaxf(fmaxf(h_prev.x, h_curr.x), h_next.x), v_curr.x);
        o.y = peak_val(fmaxf(fmaxf(h_prev.y, h_curr.y), h_next.y), v_curr.y);
        o.z = peak_val(fmaxf(fmaxf(h_prev.z, h_curr.z), h_next.z), v_curr.z);
        o.w = peak_val(fmaxf(fmaxf(h_prev.w, h_curr.w), h_next.w), v_curr.w);

        __stcs(reinterpret_cast<float4*>(obase + (size_t)r * W + c0), o);

        h_prev = h_curr;
        h_curr = h_next;
        v_curr = v_next;
    }
}

extern "C" void kernel_launch(void* const* d_in, const int* in_sizes, int n_in,
                              void* d_out, int out_size)
{
    const float* in  = (const float*)d_in[0];
    float*       out = (float*)d_out;
    const int planes = in_sizes[0] / (W * H);     // 16 * 17 = 272

    dim3 grid(H / ROWS_PER_BLOCK, planes);
    Heatmaps_57363583205469_kernel<<<grid, 128>>>(in, out);
}

// round 14
// speedup vs baseline: 1.2622x; 1.0029x over previous
#include <cuda_runtime.h>
#include <math_constants.h>

// Heatmaps_57363583205469: 3x3 max-pool peak mask + sigmoid gating.
//   keep = (maxpool3x3(h) == h) && (sigmoid(h) > 0.05)
//   out  = keep ? sigmoid(h) : 0
// Shapes: [16, 17, 512, 512] fp32 -> 272 planes of 512x512.
//
// CONVERGED FINAL (ncu 94.4-95.3us across runs, bench 98.8us, DRAM ~70%):
//  - 128 thr x 4 cols (float4), 64-row strips, unroll 4: regs=32 ->
//    whole 2176-CTA grid resident in ONE wave (occ ~87%).
//  - Horizontal 3-max via 2 warp shuffles (scalar-LDG alternative tripled
//    L1tex queue depth and regressed 27% — R10).
//  - Vertical 3-max via rolling 3-row register window; each element read
//    once from DRAM (+3% strip halo, L2-served).
//  - __stcs on the zero-reuse write stream.
//  - MLP_p1=4: below the cross-CTA L1tex queue-contention knee (unroll 8
//    regressed 20% — R6). No smem, no barriers.
// Measured ceiling: ~5.6 TB/s = HBM read/write-turnaround limit for a 1:1
// streaming mix; traffic is at the algorithmic floor (dense fp32 output
// mandatory); all compute pipes <36% and exonerated by direct experiment
// (R5/R6/R7/R8/R10). Further structural change: measured ~25% downside,
// no measured upside.

#define W 512
#define H 512
#define ROWS_PER_BLOCK 64
// logit(0.05f) computed in double precision: -ln(1/0.05000000074505806 - 1)
#define XTHRESH (-2.9444389643f)

__device__ __forceinline__ float4 row_hmax(const float* __restrict__ row,
                                           int c0, int lane, float4& v)
{
    v = __ldg(reinterpret_cast<const float4*>(row + c0));
    float l = __shfl_up_sync(0xffffffffu, v.w, 1);
    float r = __shfl_down_sync(0xffffffffu, v.x, 1);
    if (lane == 0)  l = (c0 == 0)       ? -CUDART_INF_F : __ldg(row + c0 - 1);
    if (lane == 31) r = (c0 + 4 >= W)   ? -CUDART_INF_F : __ldg(row + c0 + 4);
    float4 h;
    h.x = fmaxf(fmaxf(l,   v.x), v.y);
    h.y = fmaxf(fmaxf(v.x, v.y), v.z);
    h.z = fmaxf(fmaxf(v.y, v.z), v.w);
    h.w = fmaxf(fmaxf(v.z, v.w), r);
    return h;
}

__device__ __forceinline__ float peak_val(float m, float v)
{
    // sigmoid via fast EX2 + RCP (2 MUFU) — rel err ~1e-6, hides under DRAM.
    float s = __fdividef(1.0f, 1.0f + __expf(-v));
    return (m == v && v > XTHRESH) ? s : 0.0f;
}

__global__ void __launch_bounds__(128)
Heatmaps_57363583205469_kernel(const float* __restrict__ in,
                               float* __restrict__ out)
{
    const int plane = blockIdx.y;                 // 0..271  (B*K planes)
    const int strip = blockIdx.x;                 // 0..7    (64-row strips)
    const int lane  = threadIdx.x & 31;
    const int c0    = threadIdx.x << 2;           // 4 cols per thread

    const float* __restrict__ base  = in  + (size_t)plane * (W * H);
    float*       __restrict__ obase = out + (size_t)plane * (W * H);
    const int r0 = strip * ROWS_PER_BLOCK;

    const float4 ninf = make_float4(-CUDART_INF_F, -CUDART_INF_F,
                                    -CUDART_INF_F, -CUDART_INF_F);

    float4 v_curr, v_next, v_scratch;
    float4 h_prev, h_curr, h_next;

    h_prev = (r0 == 0) ? ninf
                       : row_hmax(base + (size_t)(r0 - 1) * W, c0, lane, v_scratch);
    h_curr = row_hmax(base + (size_t)r0 * W, c0, lane, v_curr);

    #pragma unroll 4
    for (int r = r0; r < r0 + ROWS_PER_BLOCK; ++r) {
        if (r + 1 < H) {
            h_next = row_hmax(base + (size_t)(r + 1) * W, c0, lane, v_next);
        } else {
            h_next = ninf;
            v_next = ninf;
        }

        float4 o;
        o.x = peak_val(fmaxf(fmaxf(h_prev.x, h_curr.x), h_next.x), v_curr.x);
        o.y = peak_val(fmaxf(fmaxf(h_prev.y, h_curr.y), h_next.y), v_curr.y);
        o.z = peak_val(fmaxf(fmaxf(h_prev.z, h_curr.z), h_next.z), v_curr.z);
        o.w = peak_val(fmaxf(fmaxf(h_prev.w, h_curr.w), h_next.w), v_curr.w);

        __stcs(reinterpret_cast<float4*>(obase + (size_t)r * W + c0), o);

        h_prev = h_curr;
        h_curr = h_next;
        v_curr = v_next;
    }
}

extern "C" void kernel_launch(void* const* d_in, const int* in_sizes, int n_in,
                              void* d_out, int out_size)
{
    const float* in  = (const float*)d_in[0];
    float*       out = (float*)d_out;
    const int planes = in_sizes[0] / (W * H);     // 16 * 17 = 272

    dim3 grid(H / ROWS_PER_BLOCK, planes);
    Heatmaps_57363583205469_kernel<<<grid, 128>>>(in, out);
}